// round 1
// baseline (speedup 1.0000x reference)
#include <cuda_runtime.h>
#include <math.h>

#define K_FR 8
#define B_SZ 8
#define CIN  512
#define COUT 256
#define H_   28
#define W_   28
#define HW   784
#define C4V  1024

// ---------------- scratch (device globals; no allocation at runtime) --------
__device__ float g_pf  [K_FR * B_SZ * COUT * HW];       // 12.8M
__device__ float g_x   [B_SZ * COUT * HW];
__device__ float g_x2  [B_SZ * COUT * HW];
__device__ float g_o1  [B_SZ * COUT * HW];
__device__ float g_h   [B_SZ * C4V * HW];               // 6.4M
__device__ float g_aS  [B_SZ * HW * HW];                // 4.9M
__device__ float g_aC  [B_SZ * COUT * COUT];
__device__ float g_col [B_SZ * COUT * 9 * HW];          // 14.5M
__device__ float g_cat [B_SZ * 2 * COUT * HW];
__device__ float g_bnA [COUT];
__device__ float g_bnB [COUT];

// ---------------- generic tiled SGEMM with fused epilogue -------------------
// C[m,n] (ldc=N) = epilogue( sum_k A(m,k)*B(k,n) )
// TA: A stored [K,M] (read A[k*lda+m]); else A stored [M,K] (A[m*lda+k])
// TB: B stored [N,K] (read B[n*ldb+k]); else B stored [K,N] (B[k*ldb+n])
// Per-z offsets: A += (z/aDiv)*aS; bias += (z/aDiv)*biS; B += z*bS; C += z*cS; resid += z*rS
// epilogue: v = acc*scale[m] + bias[m]; if(relu) v=max(v,0); if(resid) v = v*gamma + resid[m,n]
template <bool TA, bool TB>
__global__ void gemm_kernel(
    const float* __restrict__ A, const float* __restrict__ Bm, float* __restrict__ C,
    int M, int N, int Kd, int lda, int ldb,
    long aS, int aDiv, long bS, long cS,
    const float* __restrict__ scaleC, const float* __restrict__ biasC, long biS,
    int relu, const float* __restrict__ gammaPtr,
    const float* __restrict__ resid, long rS)
{
    const int z = blockIdx.z;
    A  += (long)(z / aDiv) * aS;
    Bm += (long)z * bS;
    C  += (long)z * cS;
    if (biasC) biasC += (long)(z / aDiv) * biS;
    if (resid) resid += (long)z * rS;

    __shared__ float As[16][64];
    __shared__ float Bs[16][64];

    const int tid = threadIdx.x;           // 256 threads
    const int tx = tid & 15, ty = tid >> 4;
    const int m0 = blockIdx.y * 64, n0 = blockIdx.x * 64;

    float acc[4][4] = {};

    for (int k0 = 0; k0 < Kd; k0 += 16) {
        // ---- load A tile -> As[k][m]
        if (TA) {
            #pragma unroll
            for (int i = tid; i < 1024; i += 256) {
                int k = i >> 6, m = i & 63;
                int gm = m0 + m, gk = k0 + k;
                float v = 0.f;
                if (gm < M && gk < Kd) v = A[(long)gk * lda + gm];
                As[k][m] = v;
            }
        } else {
            #pragma unroll
            for (int i = tid; i < 1024; i += 256) {
                int m = i >> 4, k = i & 15;
                int gm = m0 + m, gk = k0 + k;
                float v = 0.f;
                if (gm < M && gk < Kd) v = A[(long)gm * lda + gk];
                As[k][m] = v;
            }
        }
        // ---- load B tile -> Bs[k][n]
        if (TB) {
            #pragma unroll
            for (int i = tid; i < 1024; i += 256) {
                int n = i >> 4, k = i & 15;
                int gn = n0 + n, gk = k0 + k;
                float v = 0.f;
                if (gk < Kd && gn < N) v = Bm[(long)gn * ldb + gk];
                Bs[k][n] = v;
            }
        } else {
            #pragma unroll
            for (int i = tid; i < 1024; i += 256) {
                int k = i >> 6, n = i & 63;
                int gn = n0 + n, gk = k0 + k;
                float v = 0.f;
                if (gk < Kd && gn < N) v = Bm[(long)gk * ldb + gn];
                Bs[k][n] = v;
            }
        }
        __syncthreads();

        #pragma unroll
        for (int k = 0; k < 16; ++k) {
            float4 a4 = *reinterpret_cast<const float4*>(&As[k][ty * 4]);
            float4 b4 = *reinterpret_cast<const float4*>(&Bs[k][tx * 4]);
            float a[4] = {a4.x, a4.y, a4.z, a4.w};
            float b[4] = {b4.x, b4.y, b4.z, b4.w};
            #pragma unroll
            for (int i = 0; i < 4; ++i)
                #pragma unroll
                for (int j = 0; j < 4; ++j)
                    acc[i][j] = fmaf(a[i], b[j], acc[i][j]);
        }
        __syncthreads();
    }

    const float gmv = gammaPtr ? *gammaPtr : 1.f;
    #pragma unroll
    for (int i = 0; i < 4; ++i) {
        int m = m0 + ty * 4 + i;
        if (m >= M) continue;
        float sc = scaleC ? scaleC[m] : 1.f;
        float bi = biasC ? biasC[m] : 0.f;
        #pragma unroll
        for (int j = 0; j < 4; ++j) {
            int n = n0 + tx * 4 + j;
            if (n >= N) continue;
            float v = acc[i][j] * sc + bi;
            if (relu) v = fmaxf(v, 0.f);
            if (resid) v = v * gmv + resid[(long)m * N + n];
            C[(long)m * N + n] = v;
        }
    }
}

// ---------------- pointwise kernels -----------------------------------------
__global__ void tshuffle_kernel(const float* __restrict__ pf,
                                const float* __restrict__ gw,
                                const float* __restrict__ gb,
                                float* __restrict__ out)
{
    int idx = blockIdx.x * blockDim.x + threadIdx.x;   // over B*COUT*HW
    if (idx >= B_SZ * COUT * HW) return;
    int c = (idx / HW) % COUT;
    float s = gb[c];
    #pragma unroll
    for (int k = 0; k < K_FR; ++k)
        s = fmaf(pf[(long)k * (B_SZ * COUT * HW) + idx], gw[c * K_FR + k], s);
    out[idx] = s;
}

__global__ void bnprep_kernel(const float* __restrict__ p,
                              float* __restrict__ a, float* __restrict__ b)
{
    int c = blockIdx.x * blockDim.x + threadIdx.x;
    if (c >= COUT) return;
    float g = p[c], be = p[COUT + c], m = p[2 * COUT + c], v = p[3 * COUT + c];
    float s = g * rsqrtf(v + 1e-5f);
    a[c] = s;
    b[c] = be - m * s;
}

__global__ void im2col_kernel(const float* __restrict__ x, float* __restrict__ col)
{
    long idx = (long)blockIdx.x * blockDim.x + threadIdx.x;
    const long total = (long)B_SZ * COUT * 9 * HW;
    if (idx >= total) return;
    int n = (int)(idx % HW);
    long r = idx / HW;
    int t = (int)(r % 9);  r /= 9;
    int ci = (int)(r % COUT);
    int b = (int)(r / COUT);
    int h = n / W_, w = n % W_;
    int hh = h + t / 3 - 1, ww = w + t % 3 - 1;
    float v = 0.f;
    if (hh >= 0 && hh < H_ && ww >= 0 && ww < W_)
        v = x[((long)b * COUT + ci) * HW + hh * W_ + ww];
    col[idx] = v;
}

__global__ void softmax_kernel(float* __restrict__ S, int len, float scale)
{
    float* p = S + (long)blockIdx.x * len;
    __shared__ float red[256];
    int tid = threadIdx.x;
    float mx = -1e30f;
    for (int j = tid; j < len; j += 256) mx = fmaxf(mx, p[j] * scale);
    red[tid] = mx; __syncthreads();
    for (int s = 128; s > 0; s >>= 1) {
        if (tid < s) red[tid] = fmaxf(red[tid], red[tid + s]);
        __syncthreads();
    }
    mx = red[0]; __syncthreads();
    float sum = 0.f;
    for (int j = tid; j < len; j += 256) {
        float e = expf(p[j] * scale - mx);
        p[j] = e; sum += e;
    }
    red[tid] = sum; __syncthreads();
    for (int s = 128; s > 0; s >>= 1) {
        if (tid < s) red[tid] += red[tid + s];
        __syncthreads();
    }
    float inv = 1.f / red[0];
    for (int j = tid; j < len; j += 256) p[j] *= inv;
}

__global__ void concat_kernel(const float* __restrict__ kf,
                              const float* __restrict__ x,
                              float* __restrict__ cat)
{
    long idx = (long)blockIdx.x * blockDim.x + threadIdx.x;
    const long total = (long)B_SZ * 2 * COUT * HW;
    if (idx >= total) return;
    int n = (int)(idx % HW);
    long r = idx / HW;
    int c = (int)(r % (2 * COUT));
    int b = (int)(r / (2 * COUT));
    cat[idx] = (c < COUT) ? kf[((long)b * COUT + c) * HW + n]
                          : x[((long)b * COUT + (c - COUT)) * HW + n];
}

// ---------------- host-side helpers -----------------------------------------
static void launch_gemm(bool TA, bool TB,
                        const float* A, const float* B, float* C,
                        int M, int N, int Kd, int lda, int ldb,
                        long aS, int aDiv, long bS, long cS,
                        const float* sc, const float* bi, long biS,
                        int relu, const float* gp,
                        const float* res, long rS, int Z)
{
    dim3 grid((N + 63) / 64, (M + 63) / 64, Z);
    dim3 block(256);
    if (!TA && !TB)
        gemm_kernel<false, false><<<grid, block>>>(A, B, C, M, N, Kd, lda, ldb,
            aS, aDiv, bS, cS, sc, bi, biS, relu, gp, res, rS);
    else if (TA && !TB)
        gemm_kernel<true, false><<<grid, block>>>(A, B, C, M, N, Kd, lda, ldb,
            aS, aDiv, bS, cS, sc, bi, biS, relu, gp, res, rS);
    else if (!TA && TB)
        gemm_kernel<false, true><<<grid, block>>>(A, B, C, M, N, Kd, lda, ldb,
            aS, aDiv, bS, cS, sc, bi, biS, relu, gp, res, rS);
    else
        gemm_kernel<true, true><<<grid, block>>>(A, B, C, M, N, Kd, lda, ldb,
            aS, aDiv, bS, cS, sc, bi, biS, relu, gp, res, rS);
}

extern "C" void kernel_launch(void* const* d_in, const int* in_sizes, int n_in,
                              void* d_out, int out_size)
{
    const float* feats    = (const float*)d_in[0];
    const float* proj_w   = (const float*)d_in[1];
    const float* proj_b   = (const float*)d_in[2];
    const float* ts_gw    = (const float*)d_in[3];
    const float* ts_gb    = (const float*)d_in[4];
    const float* ts_w3    = (const float*)d_in[5];
    const float* ts_bn    = (const float*)d_in[6];
    const float* ssam_w1  = (const float*)d_in[7];
    const float* ssam_b1  = (const float*)d_in[8];
    const float* ssam_w2  = (const float*)d_in[9];
    const float* ssam_b2  = (const float*)d_in[10];
    const float* ssam_g   = (const float*)d_in[11];
    const float* csam_w1  = (const float*)d_in[12];
    const float* csam_b1  = (const float*)d_in[13];
    const float* csam_w2  = (const float*)d_in[14];
    const float* csam_b2  = (const float*)d_in[15];
    const float* fuse_w1  = (const float*)d_in[16];
    const float* fuse_bn1 = (const float*)d_in[17];
    const float* fuse_w2  = (const float*)d_in[18];
    const float* fuse_bn2 = (const float*)d_in[19];
    const float* fcsam_w1 = (const float*)d_in[20];
    const float* fcsam_b1 = (const float*)d_in[21];
    const float* fcsam_w2 = (const float*)d_in[22];
    const float* fcsam_b2 = (const float*)d_in[23];
    const float* fuse_w4  = (const float*)d_in[24];
    const float* fuse_bn4 = (const float*)d_in[25];
    float* out = (float*)d_out;

    float *pf, *x, *x2, *o1, *h, *aS_, *aC_, *col, *cat, *bnA, *bnB;
    cudaGetSymbolAddress((void**)&pf,  g_pf);
    cudaGetSymbolAddress((void**)&x,   g_x);
    cudaGetSymbolAddress((void**)&x2,  g_x2);
    cudaGetSymbolAddress((void**)&o1,  g_o1);
    cudaGetSymbolAddress((void**)&h,   g_h);
    cudaGetSymbolAddress((void**)&aS_, g_aS);
    cudaGetSymbolAddress((void**)&aC_, g_aC);
    cudaGetSymbolAddress((void**)&col, g_col);
    cudaGetSymbolAddress((void**)&cat, g_cat);
    cudaGetSymbolAddress((void**)&bnA, g_bnA);
    cudaGetSymbolAddress((void**)&bnB, g_bnB);

    const long SP  = (long)COUT * HW;       // 200704  per-(k,b) plane
    const long SPH = (long)C4V * HW;        // 802816
    const long SPS = (long)HW * HW;         // 614656
    const long SPC = (long)COUT * COUT;     // 65536
    const long SPCOL = (long)COUT * 9 * HW; // 1806336
    const long SPCAT = (long)2 * COUT * HW; // 401408

    // 1. per-frame 1x1 projection: pf[k,b] = proj_w[k] @ feats[k,b] + proj_b[k]
    launch_gemm(false, false, proj_w, feats, pf, COUT, HW, CIN, CIN, HW,
                (long)COUT * CIN, B_SZ, (long)CIN * HW, SP,
                nullptr, proj_b, COUT, 0, nullptr, nullptr, 0, K_FR * B_SZ);

    // 2. temporal shuffle + grouped 1x1 -> x
    {
        int total = B_SZ * COUT * HW;
        tshuffle_kernel<<<(total + 255) / 256, 256>>>(pf, ts_gw, ts_gb, x);
    }

    // 3. 3x3 conv + BN -> x2
    bnprep_kernel<<<1, 256>>>(ts_bn, bnA, bnB);
    {
        long total = (long)B_SZ * SPCOL;
        im2col_kernel<<<(int)((total + 255) / 256), 256>>>(x, col);
    }
    launch_gemm(false, false, ts_w3, col, x2, COUT, HW, COUT * 9, COUT * 9, HW,
                0, 1, SPCOL, SP, bnA, bnB, 0, 0, nullptr, nullptr, 0, B_SZ);

    // 4. spatial self-attention (input x2, output x)
    launch_gemm(true, false, x2, x2, aS_, HW, HW, COUT, HW, HW,
                SP, 1, SP, SPS, nullptr, nullptr, 0, 0, nullptr, nullptr, 0, B_SZ);
    softmax_kernel<<<B_SZ * HW, 256>>>(aS_, HW, 0.0625f);
    launch_gemm(false, true, x2, aS_, o1, COUT, HW, HW, HW, HW,
                SP, 1, SPS, SP, nullptr, nullptr, 0, 0, nullptr, nullptr, 0, B_SZ);
    launch_gemm(false, false, ssam_w1, o1, h, C4V, HW, COUT, COUT, HW,
                0, 1, SP, SPH, nullptr, ssam_b1, 0, 1, nullptr, nullptr, 0, B_SZ);
    launch_gemm(false, false, ssam_w2, h, x, COUT, HW, C4V, C4V, HW,
                0, 1, SPH, SP, nullptr, ssam_b2, 0, 0, ssam_g, x2, SP, B_SZ);

    // 5. channel self-attention (input x, output x2)
    launch_gemm(false, true, x, x, aC_, COUT, COUT, HW, HW, HW,
                SP, 1, SP, SPC, nullptr, nullptr, 0, 0, nullptr, nullptr, 0, B_SZ);
    softmax_kernel<<<B_SZ * COUT, 256>>>(aC_, COUT, 0.0625f);
    launch_gemm(false, false, aC_, x, o1, COUT, HW, COUT, COUT, HW,
                SPC, 1, SP, SP, nullptr, nullptr, 0, 0, nullptr, nullptr, 0, B_SZ);
    launch_gemm(false, false, csam_w1, o1, h, C4V, HW, COUT, COUT, HW,
                0, 1, SP, SPH, nullptr, csam_b1, 0, 1, nullptr, nullptr, 0, B_SZ);
    launch_gemm(false, false, csam_w2, h, x2, COUT, HW, C4V, C4V, HW,
                0, 1, SPH, SP, nullptr, csam_b2, 0, 0, nullptr, x, SP, B_SZ);

    // 6. fuse: concat keyframe feat (pf[K-1]) with x2
    {
        long total = (long)B_SZ * SPCAT;
        concat_kernel<<<(int)((total + 255) / 256), 256>>>(
            pf + (long)(K_FR - 1) * B_SZ * SP, x2, cat);
    }
    bnprep_kernel<<<1, 256>>>(fuse_bn1, bnA, bnB);
    launch_gemm(false, false, fuse_w1, cat, x, COUT, HW, 2 * COUT, 2 * COUT, HW,
                0, 1, SPCAT, SP, bnA, bnB, 0, 1, nullptr, nullptr, 0, B_SZ);

    // 7. 3x3 conv + BN + relu -> x2
    bnprep_kernel<<<1, 256>>>(fuse_bn2, bnA, bnB);
    {
        long total = (long)B_SZ * SPCOL;
        im2col_kernel<<<(int)((total + 255) / 256), 256>>>(x, col);
    }
    launch_gemm(false, false, fuse_w2, col, x2, COUT, HW, COUT * 9, COUT * 9, HW,
                0, 1, SPCOL, SP, bnA, bnB, 0, 1, nullptr, nullptr, 0, B_SZ);

    // 8. channel self-attention (input x2, output x)
    launch_gemm(false, true, x2, x2, aC_, COUT, COUT, HW, HW, HW,
                SP, 1, SP, SPC, nullptr, nullptr, 0, 0, nullptr, nullptr, 0, B_SZ);
    softmax_kernel<<<B_SZ * COUT, 256>>>(aC_, COUT, 0.0625f);
    launch_gemm(false, false, aC_, x2, o1, COUT, HW, COUT, COUT, HW,
                SPC, 1, SP, SP, nullptr, nullptr, 0, 0, nullptr, nullptr, 0, B_SZ);
    launch_gemm(false, false, fcsam_w1, o1, h, C4V, HW, COUT, COUT, HW,
                0, 1, SP, SPH, nullptr, fcsam_b1, 0, 1, nullptr, nullptr, 0, B_SZ);
    launch_gemm(false, false, fcsam_w2, h, x, COUT, HW, C4V, C4V, HW,
                0, 1, SPH, SP, nullptr, fcsam_b2, 0, 0, nullptr, x2, SP, B_SZ);

    // 9. final 3x3 conv + BN + relu -> d_out
    bnprep_kernel<<<1, 256>>>(fuse_bn4, bnA, bnB);
    {
        long total = (long)B_SZ * SPCOL;
        im2col_kernel<<<(int)((total + 255) / 256), 256>>>(x, col);
    }
    launch_gemm(false, false, fuse_w4, col, out, COUT, HW, COUT * 9, COUT * 9, HW,
                0, 1, SPCOL, SP, bnA, bnB, 0, 1, nullptr, nullptr, 0, B_SZ);
}

// round 3
// speedup vs baseline: 1.3867x; 1.3867x over previous
#include <cuda_runtime.h>
#include <math.h>

#define K_FR 8
#define B_SZ 8
#define CIN  512
#define COUT 256
#define H_   28
#define W_   28
#define HW   784
#define C4V  1024

// ---------------- scratch (device globals; no allocation at runtime) --------
__device__ float g_pf  [K_FR * B_SZ * COUT * HW];
__device__ float g_x   [B_SZ * COUT * HW];
__device__ float g_x2  [B_SZ * COUT * HW];
__device__ float g_o1  [B_SZ * COUT * HW];
__device__ float g_h   [B_SZ * C4V * HW];
__device__ float g_aS  [B_SZ * HW * HW];
__device__ float g_aC  [B_SZ * COUT * COUT];
__device__ float g_col [B_SZ * COUT * 9 * HW];
__device__ float g_cat [B_SZ * 2 * COUT * HW];
__device__ float g_bnA [COUT];
__device__ float g_bnB [COUT];

// ---------------- 3xTF32 tensor-core GEMM ------------------------------------
// C[m,n] = epilogue( sum_k A(m,k)*B(k,n) ), tiles 128x128x16, mma.m16n8k8 tf32,
// 3xTF32 error compensation: a*b ~= aH*bH + aH*bL + aL*bH  (fp32-level accuracy)
// TA: A stored [K,M]; else [M,K].  TB: B stored [N,K]; else [K,N].
// Per-z: A += (z/aDiv)*aS; bias += (z/aDiv)*biS; B += z*bS; C += z*cS; resid += z*rS
// epilogue: v = acc*scale[m]+bias[m]; relu; v = v*gamma + resid[m,n]
// Requires Kd % 16 == 0 (true for all call sites: 256/512/784/1024/2304).

__device__ __forceinline__ unsigned f2tf(float f) {
    unsigned u;
    asm("cvt.rna.tf32.f32 %0, %1;" : "=r"(u) : "f"(f));
    return u;
}

// hi = tf32(f); lo = tf32(f - hi)   (residual split, exact subtraction)
__device__ __forceinline__ void f2tf_split(float f, unsigned& hi, unsigned& lo) {
    hi = f2tf(f);
    lo = f2tf(f - __uint_as_float(hi));
}

__device__ __forceinline__ void mma_tf32(float4& d, const unsigned a[4], const unsigned b[2]) {
    asm volatile(
        "mma.sync.aligned.m16n8k8.row.col.f32.tf32.tf32.f32 "
        "{%0,%1,%2,%3}, {%4,%5,%6,%7}, {%8,%9}, {%0,%1,%2,%3};"
        : "+f"(d.x), "+f"(d.y), "+f"(d.z), "+f"(d.w)
        : "r"(a[0]), "r"(a[1]), "r"(a[2]), "r"(a[3]), "r"(b[0]), "r"(b[1]));
}

#define BKP 24   // padded smem stride: rows map to bank bases {0,24,16,8} -> conflict-free

template <bool TA, bool TB>
__global__ void __launch_bounds__(256) gemm_tc(
    const float* __restrict__ A, const float* __restrict__ Bm, float* __restrict__ C,
    int M, int N, int Kd, int lda, int ldb,
    long aS, int aDiv, long bS, long cS,
    const float* __restrict__ scaleC, const float* __restrict__ biasC, long biS,
    int relu, const float* __restrict__ gammaPtr,
    const float* __restrict__ resid, long rS)
{
    const int z = blockIdx.z;
    A  += (long)(z / aDiv) * aS;
    Bm += (long)z * bS;
    C  += (long)z * cS;
    if (biasC) biasC += (long)(z / aDiv) * biS;
    if (resid) resid += (long)z * rS;

    __shared__ __align__(16) float As[2][128][BKP];
    __shared__ __align__(16) float Bs[2][128][BKP];

    const int tid  = threadIdx.x;
    const int lane = tid & 31, warp = tid >> 5;
    const int wm = (warp >> 2) * 64;   // warp row offset (2 rows of warps)
    const int wn = (warp & 3) * 32;    // warp col offset (4 cols of warps)
    const int m0 = blockIdx.y * 128, n0 = blockIdx.x * 128;

    float4 acc[4][4];
    #pragma unroll
    for (int i = 0; i < 4; ++i)
        #pragma unroll
        for (int j = 0; j < 4; ++j)
            acc[i][j] = make_float4(0.f, 0.f, 0.f, 0.f);

    float ra[8], rb[8];

    auto loadA = [&](int k0) {
        #pragma unroll
        for (int t = 0; t < 8; ++t) {
            int i = tid + t * 256;
            int m, k;
            if (TA) { m = i & 127; k = i >> 7; }
            else    { k = i & 15;  m = i >> 4; }
            int gm = m0 + m, gk = k0 + k;
            float v = 0.f;
            if (gm < M) v = TA ? A[(long)gk * lda + gm] : A[(long)gm * lda + gk];
            ra[t] = v;
        }
    };
    auto loadB = [&](int k0) {
        #pragma unroll
        for (int t = 0; t < 8; ++t) {
            int i = tid + t * 256;
            int n, k;
            if (TB) { k = i & 15;  n = i >> 4; }
            else    { n = i & 127; k = i >> 7; }
            int gn = n0 + n, gk = k0 + k;
            float v = 0.f;
            if (gn < N) v = TB ? Bm[(long)gn * ldb + gk] : Bm[(long)gk * ldb + gn];
            rb[t] = v;
        }
    };
    auto storeA = [&](int buf) {
        #pragma unroll
        for (int t = 0; t < 8; ++t) {
            int i = tid + t * 256;
            int m, k;
            if (TA) { m = i & 127; k = i >> 7; }
            else    { k = i & 15;  m = i >> 4; }
            int pc = ((k >> 3) << 3) + ((k & 3) << 1) + ((k >> 2) & 1);
            As[buf][m][pc] = ra[t];
        }
    };
    auto storeB = [&](int buf) {
        #pragma unroll
        for (int t = 0; t < 8; ++t) {
            int i = tid + t * 256;
            int n, k;
            if (TB) { k = i & 15;  n = i >> 4; }
            else    { n = i & 127; k = i >> 7; }
            int pc = ((k >> 3) << 3) + ((k & 3) << 1) + ((k >> 2) & 1);
            Bs[buf][n][pc] = rb[t];
        }
    };
    auto compute = [&](int buf) {
        #pragma unroll
        for (int g = 0; g < 2; ++g) {
            unsigned aH[4][4], aL[4][4], bH[4][2], bL[4][2];
            #pragma unroll
            for (int i = 0; i < 4; ++i) {
                int r = wm + i * 16 + (lane >> 2);
                float2 t0 = *(const float2*)&As[buf][r][g * 8 + ((lane & 3) << 1)];
                float2 t1 = *(const float2*)&As[buf][r + 8][g * 8 + ((lane & 3) << 1)];
                f2tf_split(t0.x, aH[i][0], aL[i][0]);
                f2tf_split(t1.x, aH[i][1], aL[i][1]);
                f2tf_split(t0.y, aH[i][2], aL[i][2]);
                f2tf_split(t1.y, aH[i][3], aL[i][3]);
            }
            #pragma unroll
            for (int j = 0; j < 4; ++j) {
                int c = wn + j * 8 + (lane >> 2);
                float2 u = *(const float2*)&Bs[buf][c][g * 8 + ((lane & 3) << 1)];
                f2tf_split(u.x, bH[j][0], bL[j][0]);
                f2tf_split(u.y, bH[j][1], bL[j][1]);
            }
            #pragma unroll
            for (int i = 0; i < 4; ++i)
                #pragma unroll
                for (int j = 0; j < 4; ++j) {
                    mma_tf32(acc[i][j], aH[i], bH[j]);   // hi*hi
                    mma_tf32(acc[i][j], aH[i], bL[j]);   // hi*lo
                    mma_tf32(acc[i][j], aL[i], bH[j]);   // lo*hi
                }
        }
    };

    int buf = 0;
    loadA(0); loadB(0);
    storeA(0); storeB(0);
    __syncthreads();

    for (int k0 = 0; k0 < Kd; k0 += 16) {
        bool more = (k0 + 16) < Kd;
        if (more) { loadA(k0 + 16); loadB(k0 + 16); }
        compute(buf);
        if (more) {
            storeA(buf ^ 1); storeB(buf ^ 1);
            __syncthreads();
            buf ^= 1;
        }
    }

    const float gmv = gammaPtr ? *gammaPtr : 1.f;
    #pragma unroll
    for (int i = 0; i < 4; ++i) {
        int r0 = m0 + wm + i * 16 + (lane >> 2);
        int r1 = r0 + 8;
        float sc0 = 1.f, bi0 = 0.f, sc1 = 1.f, bi1 = 0.f;
        if (scaleC) { if (r0 < M) sc0 = scaleC[r0]; if (r1 < M) sc1 = scaleC[r1]; }
        if (biasC)  { if (r0 < M) bi0 = biasC[r0];  if (r1 < M) bi1 = biasC[r1]; }
        #pragma unroll
        for (int j = 0; j < 4; ++j) {
            int c = n0 + wn + j * 8 + ((lane & 3) << 1);
            float4 v = acc[i][j];
            if (r0 < M) {
                float x0 = v.x * sc0 + bi0, x1 = v.y * sc0 + bi0;
                if (relu) { x0 = fmaxf(x0, 0.f); x1 = fmaxf(x1, 0.f); }
                if (resid) {
                    if (c < N)     x0 = x0 * gmv + resid[(long)r0 * N + c];
                    if (c + 1 < N) x1 = x1 * gmv + resid[(long)r0 * N + c + 1];
                }
                if (c < N)     C[(long)r0 * N + c]     = x0;
                if (c + 1 < N) C[(long)r0 * N + c + 1] = x1;
            }
            if (r1 < M) {
                float x2_ = v.z * sc1 + bi1, x3 = v.w * sc1 + bi1;
                if (relu) { x2_ = fmaxf(x2_, 0.f); x3 = fmaxf(x3, 0.f); }
                if (resid) {
                    if (c < N)     x2_ = x2_ * gmv + resid[(long)r1 * N + c];
                    if (c + 1 < N) x3  = x3  * gmv + resid[(long)r1 * N + c + 1];
                }
                if (c < N)     C[(long)r1 * N + c]     = x2_;
                if (c + 1 < N) C[(long)r1 * N + c + 1] = x3;
            }
        }
    }
}

// ---------------- pointwise kernels -----------------------------------------
__global__ void tshuffle_kernel(const float* __restrict__ pf,
                                const float* __restrict__ gw,
                                const float* __restrict__ gb,
                                float* __restrict__ out)
{
    int idx = blockIdx.x * blockDim.x + threadIdx.x;
    if (idx >= B_SZ * COUT * HW) return;
    int c = (idx / HW) % COUT;
    float s = gb[c];
    #pragma unroll
    for (int k = 0; k < K_FR; ++k)
        s = fmaf(pf[(long)k * (B_SZ * COUT * HW) + idx], gw[c * K_FR + k], s);
    out[idx] = s;
}

__global__ void bnprep_kernel(const float* __restrict__ p,
                              float* __restrict__ a, float* __restrict__ b)
{
    int c = blockIdx.x * blockDim.x + threadIdx.x;
    if (c >= COUT) return;
    float g = p[c], be = p[COUT + c], m = p[2 * COUT + c], v = p[3 * COUT + c];
    float s = g * rsqrtf(v + 1e-5f);
    a[c] = s;
    b[c] = be - m * s;
}

__global__ void im2col_kernel(const float* __restrict__ x, float* __restrict__ col)
{
    long idx = (long)blockIdx.x * blockDim.x + threadIdx.x;
    const long total = (long)B_SZ * COUT * 9 * HW;
    if (idx >= total) return;
    int n = (int)(idx % HW);
    long r = idx / HW;
    int t = (int)(r % 9);  r /= 9;
    int ci = (int)(r % COUT);
    int b = (int)(r / COUT);
    int h = n / W_, w = n % W_;
    int hh = h + t / 3 - 1, ww = w + t % 3 - 1;
    float v = 0.f;
    if (hh >= 0 && hh < H_ && ww >= 0 && ww < W_)
        v = x[((long)b * COUT + ci) * HW + hh * W_ + ww];
    col[idx] = v;
}

__global__ void softmax_kernel(float* __restrict__ S, int len, float scale)
{
    float* p = S + (long)blockIdx.x * len;
    __shared__ float red[256];
    int tid = threadIdx.x;
    float mx = -1e30f;
    for (int j = tid; j < len; j += 256) mx = fmaxf(mx, p[j] * scale);
    red[tid] = mx; __syncthreads();
    for (int s = 128; s > 0; s >>= 1) {
        if (tid < s) red[tid] = fmaxf(red[tid], red[tid + s]);
        __syncthreads();
    }
    mx = red[0]; __syncthreads();
    float sum = 0.f;
    for (int j = tid; j < len; j += 256) {
        float e = expf(p[j] * scale - mx);
        p[j] = e; sum += e;
    }
    red[tid] = sum; __syncthreads();
    for (int s = 128; s > 0; s >>= 1) {
        if (tid < s) red[tid] += red[tid + s];
        __syncthreads();
    }
    float inv = 1.f / red[0];
    for (int j = tid; j < len; j += 256) p[j] *= inv;
}

__global__ void concat_kernel(const float* __restrict__ kf,
                              const float* __restrict__ x,
                              float* __restrict__ cat)
{
    long idx = (long)blockIdx.x * blockDim.x + threadIdx.x;
    const long total = (long)B_SZ * 2 * COUT * HW;
    if (idx >= total) return;
    int n = (int)(idx % HW);
    long r = idx / HW;
    int c = (int)(r % (2 * COUT));
    int b = (int)(r / (2 * COUT));
    cat[idx] = (c < COUT) ? kf[((long)b * COUT + c) * HW + n]
                          : x[((long)b * COUT + (c - COUT)) * HW + n];
}

// ---------------- host-side helpers -----------------------------------------
static void launch_gemm(bool TA, bool TB,
                        const float* A, const float* B, float* C,
                        int M, int N, int Kd, int lda, int ldb,
                        long aS, int aDiv, long bS, long cS,
                        const float* sc, const float* bi, long biS,
                        int relu, const float* gp,
                        const float* res, long rS, int Z)
{
    dim3 grid((N + 127) / 128, (M + 127) / 128, Z);
    dim3 block(256);
    if (!TA && !TB)
        gemm_tc<false, false><<<grid, block>>>(A, B, C, M, N, Kd, lda, ldb,
            aS, aDiv, bS, cS, sc, bi, biS, relu, gp, res, rS);
    else if (TA && !TB)
        gemm_tc<true, false><<<grid, block>>>(A, B, C, M, N, Kd, lda, ldb,
            aS, aDiv, bS, cS, sc, bi, biS, relu, gp, res, rS);
    else if (!TA && TB)
        gemm_tc<false, true><<<grid, block>>>(A, B, C, M, N, Kd, lda, ldb,
            aS, aDiv, bS, cS, sc, bi, biS, relu, gp, res, rS);
    else
        gemm_tc<true, true><<<grid, block>>>(A, B, C, M, N, Kd, lda, ldb,
            aS, aDiv, bS, cS, sc, bi, biS, relu, gp, res, rS);
}

extern "C" void kernel_launch(void* const* d_in, const int* in_sizes, int n_in,
                              void* d_out, int out_size)
{
    const float* feats    = (const float*)d_in[0];
    const float* proj_w   = (const float*)d_in[1];
    const float* proj_b   = (const float*)d_in[2];
    const float* ts_gw    = (const float*)d_in[3];
    const float* ts_gb    = (const float*)d_in[4];
    const float* ts_w3    = (const float*)d_in[5];
    const float* ts_bn    = (const float*)d_in[6];
    const float* ssam_w1  = (const float*)d_in[7];
    const float* ssam_b1  = (const float*)d_in[8];
    const float* ssam_w2  = (const float*)d_in[9];
    const float* ssam_b2  = (const float*)d_in[10];
    const float* ssam_g   = (const float*)d_in[11];
    const float* csam_w1  = (const float*)d_in[12];
    const float* csam_b1  = (const float*)d_in[13];
    const float* csam_w2  = (const float*)d_in[14];
    const float* csam_b2  = (const float*)d_in[15];
    const float* fuse_w1  = (const float*)d_in[16];
    const float* fuse_bn1 = (const float*)d_in[17];
    const float* fuse_w2  = (const float*)d_in[18];
    const float* fuse_bn2 = (const float*)d_in[19];
    const float* fcsam_w1 = (const float*)d_in[20];
    const float* fcsam_b1 = (const float*)d_in[21];
    const float* fcsam_w2 = (const float*)d_in[22];
    const float* fcsam_b2 = (const float*)d_in[23];
    const float* fuse_w4  = (const float*)d_in[24];
    const float* fuse_bn4 = (const float*)d_in[25];
    float* out = (float*)d_out;

    float *pf, *x, *x2, *o1, *h, *aS_, *aC_, *col, *cat, *bnA, *bnB;
    cudaGetSymbolAddress((void**)&pf,  g_pf);
    cudaGetSymbolAddress((void**)&x,   g_x);
    cudaGetSymbolAddress((void**)&x2,  g_x2);
    cudaGetSymbolAddress((void**)&o1,  g_o1);
    cudaGetSymbolAddress((void**)&h,   g_h);
    cudaGetSymbolAddress((void**)&aS_, g_aS);
    cudaGetSymbolAddress((void**)&aC_, g_aC);
    cudaGetSymbolAddress((void**)&col, g_col);
    cudaGetSymbolAddress((void**)&cat, g_cat);
    cudaGetSymbolAddress((void**)&bnA, g_bnA);
    cudaGetSymbolAddress((void**)&bnB, g_bnB);

    const long SP  = (long)COUT * HW;
    const long SPH = (long)C4V * HW;
    const long SPS = (long)HW * HW;
    const long SPC = (long)COUT * COUT;
    const long SPCOL = (long)COUT * 9 * HW;
    const long SPCAT = (long)2 * COUT * HW;

    // 1. per-frame 1x1 projection
    launch_gemm(false, false, proj_w, feats, pf, COUT, HW, CIN, CIN, HW,
                (long)COUT * CIN, B_SZ, (long)CIN * HW, SP,
                nullptr, proj_b, COUT, 0, nullptr, nullptr, 0, K_FR * B_SZ);

    // 2. temporal shuffle + grouped 1x1 -> x
    {
        int total = B_SZ * COUT * HW;
        tshuffle_kernel<<<(total + 255) / 256, 256>>>(pf, ts_gw, ts_gb, x);
    }

    // 3. 3x3 conv + BN -> x2
    bnprep_kernel<<<1, 256>>>(ts_bn, bnA, bnB);
    {
        long total = (long)B_SZ * SPCOL;
        im2col_kernel<<<(int)((total + 255) / 256), 256>>>(x, col);
    }
    launch_gemm(false, false, ts_w3, col, x2, COUT, HW, COUT * 9, COUT * 9, HW,
                0, 1, SPCOL, SP, bnA, bnB, 0, 0, nullptr, nullptr, 0, B_SZ);

    // 4. spatial self-attention (input x2, output x)
    launch_gemm(true, false, x2, x2, aS_, HW, HW, COUT, HW, HW,
                SP, 1, SP, SPS, nullptr, nullptr, 0, 0, nullptr, nullptr, 0, B_SZ);
    softmax_kernel<<<B_SZ * HW, 256>>>(aS_, HW, 0.0625f);
    launch_gemm(false, true, x2, aS_, o1, COUT, HW, HW, HW, HW,
                SP, 1, SPS, SP, nullptr, nullptr, 0, 0, nullptr, nullptr, 0, B_SZ);
    launch_gemm(false, false, ssam_w1, o1, h, C4V, HW, COUT, COUT, HW,
                0, 1, SP, SPH, nullptr, ssam_b1, 0, 1, nullptr, nullptr, 0, B_SZ);
    launch_gemm(false, false, ssam_w2, h, x, COUT, HW, C4V, C4V, HW,
                0, 1, SPH, SP, nullptr, ssam_b2, 0, 0, ssam_g, x2, SP, B_SZ);

    // 5. channel self-attention (input x, output x2)
    launch_gemm(false, true, x, x, aC_, COUT, COUT, HW, HW, HW,
                SP, 1, SP, SPC, nullptr, nullptr, 0, 0, nullptr, nullptr, 0, B_SZ);
    softmax_kernel<<<B_SZ * COUT, 256>>>(aC_, COUT, 0.0625f);
    launch_gemm(false, false, aC_, x, o1, COUT, HW, COUT, COUT, HW,
                SPC, 1, SP, SP, nullptr, nullptr, 0, 0, nullptr, nullptr, 0, B_SZ);
    launch_gemm(false, false, csam_w1, o1, h, C4V, HW, COUT, COUT, HW,
                0, 1, SP, SPH, nullptr, csam_b1, 0, 1, nullptr, nullptr, 0, B_SZ);
    launch_gemm(false, false, csam_w2, h, x2, COUT, HW, C4V, C4V, HW,
                0, 1, SPH, SP, nullptr, csam_b2, 0, 0, nullptr, x, SP, B_SZ);

    // 6. fuse: concat keyframe feat (pf[K-1]) with x2
    {
        long total = (long)B_SZ * SPCAT;
        concat_kernel<<<(int)((total + 255) / 256), 256>>>(
            pf + (long)(K_FR - 1) * B_SZ * SP, x2, cat);
    }
    bnprep_kernel<<<1, 256>>>(fuse_bn1, bnA, bnB);
    launch_gemm(false, false, fuse_w1, cat, x, COUT, HW, 2 * COUT, 2 * COUT, HW,
                0, 1, SPCAT, SP, bnA, bnB, 0, 1, nullptr, nullptr, 0, B_SZ);

    // 7. 3x3 conv + BN + relu -> x2
    bnprep_kernel<<<1, 256>>>(fuse_bn2, bnA, bnB);
    {
        long total = (long)B_SZ * SPCOL;
        im2col_kernel<<<(int)((total + 255) / 256), 256>>>(x, col);
    }
    launch_gemm(false, false, fuse_w2, col, x2, COUT, HW, COUT * 9, COUT * 9, HW,
                0, 1, SPCOL, SP, bnA, bnB, 0, 1, nullptr, nullptr, 0, B_SZ);

    // 8. channel self-attention (input x2, output x)
    launch_gemm(false, true, x2, x2, aC_, COUT, COUT, HW, HW, HW,
                SP, 1, SP, SPC, nullptr, nullptr, 0, 0, nullptr, nullptr, 0, B_SZ);
    softmax_kernel<<<B_SZ * COUT, 256>>>(aC_, COUT, 0.0625f);
    launch_gemm(false, false, aC_, x2, o1, COUT, HW, COUT, COUT, HW,
                SPC, 1, SP, SP, nullptr, nullptr, 0, 0, nullptr, nullptr, 0, B_SZ);
    launch_gemm(false, false, fcsam_w1, o1, h, C4V, HW, COUT, COUT, HW,
                0, 1, SP, SPH, nullptr, fcsam_b1, 0, 1, nullptr, nullptr, 0, B_SZ);
    launch_gemm(false, false, fcsam_w2, h, x, COUT, HW, C4V, C4V, HW,
                0, 1, SPH, SP, nullptr, fcsam_b2, 0, 0, nullptr, x2, SP, B_SZ);

    // 9. final 3x3 conv + BN + relu -> d_out
    bnprep_kernel<<<1, 256>>>(fuse_bn4, bnA, bnB);
    {
        long total = (long)B_SZ * SPCOL;
        im2col_kernel<<<(int)((total + 255) / 256), 256>>>(x, col);
    }
    launch_gemm(false, false, fuse_w4, col, out, COUT, HW, COUT * 9, COUT * 9, HW,
                0, 1, SPCOL, SP, bnA, bnB, 0, 1, nullptr, nullptr, 0, B_SZ);
}

// round 4
// speedup vs baseline: 1.5286x; 1.1023x over previous
#include <cuda_runtime.h>
#include <math.h>

#define K_FR 8
#define B_SZ 8
#define CIN  512
#define COUT 256
#define H_   28
#define W_   28
#define HW   784
#define C4V  1024

// ---------------- scratch (device globals; no allocation at runtime) --------
__device__ float g_pf  [K_FR * B_SZ * COUT * HW];
__device__ float g_x   [B_SZ * COUT * HW];
__device__ float g_x2  [B_SZ * COUT * HW];
__device__ float g_o1  [B_SZ * COUT * HW];
__device__ float g_h   [B_SZ * C4V * HW];
__device__ float g_aS  [B_SZ * HW * HW];
__device__ float g_aC  [B_SZ * COUT * COUT];
__device__ float g_col [B_SZ * COUT * 9 * HW];
__device__ float g_cat [B_SZ * 2 * COUT * HW];
__device__ float g_bnA [COUT];
__device__ float g_bnB [COUT];

// ---------------- 3xTF32 tensor-core GEMM, split-at-store ------------------
// Inner loop is pure LDS.128 + HMMA. smem holds, for each value, the float4
// {hi(k), hi(k+4), lo(k), lo(k+4)} at row-stride 48 floats (conflict-free
// fragment loads: bank = 16*q + g*16 + 4*(lane&3), quarter-warp covers all 32).
// TA: A stored [K,M]; else [M,K].  TB: B stored [N,K]; else [K,N].
// epilogue: v = acc*scale[m]+bias[m]; relu; v = v*gamma + resid[m,n]
// Requires Kd % 16 == 0 (all call sites: 256/512/784/1024/2304).

__device__ __forceinline__ unsigned f2tf(float f) {
    unsigned u;
    asm("cvt.rna.tf32.f32 %0, %1;" : "=r"(u) : "f"(f));
    return u;
}
__device__ __forceinline__ void f2tf_split(float f, unsigned& hi, unsigned& lo) {
    hi = f2tf(f);
    lo = f2tf(f - __uint_as_float(hi));
}
__device__ __forceinline__ void mma_tf32(float4& d, const unsigned a[4], const unsigned b[2]) {
    asm volatile(
        "mma.sync.aligned.m16n8k8.row.col.f32.tf32.tf32.f32 "
        "{%0,%1,%2,%3}, {%4,%5,%6,%7}, {%8,%9}, {%0,%1,%2,%3};"
        : "+f"(d.x), "+f"(d.y), "+f"(d.z), "+f"(d.w)
        : "r"(a[0]), "r"(a[1]), "r"(a[2]), "r"(a[3]), "r"(b[0]), "r"(b[1]));
}

#define SSTR 48   // smem row stride in floats

template <int BM, int BN, bool TA, bool TB>
__global__ void __launch_bounds__(256) gemm_tc(
    const float* __restrict__ A, const float* __restrict__ Bm, float* __restrict__ C,
    int M, int N, int Kd, int lda, int ldb,
    long aS, int aDiv, long bS, long cS,
    const float* __restrict__ scaleC, const float* __restrict__ biasC, long biS,
    int relu, const float* __restrict__ gammaPtr,
    const float* __restrict__ resid, long rS)
{
    extern __shared__ float sm[];
    float* As = sm;                    // [2][BM][SSTR]
    float* Bs = sm + 2 * BM * SSTR;    // [2][BN][SSTR]

    const int z = blockIdx.z;
    A  += (long)(z / aDiv) * aS;
    Bm += (long)z * bS;
    C  += (long)z * cS;
    if (biasC) biasC += (long)(z / aDiv) * biS;
    if (resid) resid += (long)z * rS;

    const int tid  = threadIdx.x;
    const int lane = tid & 31, warp = tid >> 5;
    constexpr int MI = BM / 32, NJ = BN / 32;
    constexpr int LBM = (BM == 128) ? 7 : 6;
    constexpr int LBN = (BN == 128) ? 7 : 6;
    constexpr int NA = BM * 16 / 256;   // values per thread (A tile)
    constexpr int PA = NA / 2;          // pairs per thread (TA path)
    constexpr int NB = BN * 16 / 256;
    constexpr int PB = NB / 2;
    const int wm = (warp >> 2) * (BM / 2);
    const int wn = (warp & 3) * (BN / 4);
    const int m0 = blockIdx.y * BM, n0 = blockIdx.x * BN;

    float4 acc[MI][NJ];
    #pragma unroll
    for (int i = 0; i < MI; ++i)
        #pragma unroll
        for (int j = 0; j < NJ; ++j)
            acc[i][j] = make_float4(0.f, 0.f, 0.f, 0.f);

    float va[NA], vb[NB];

    auto loadA = [&](int k0) {
        if (!TA) {
            #pragma unroll
            for (int t = 0; t < NA; ++t) {
                int i = tid + t * 256;
                int k = i & 15, m = i >> 4;
                int gm = m0 + m;
                va[t] = (gm < M) ? A[(long)gm * lda + k0 + k] : 0.f;
            }
        } else {
            int m = tid & (BM - 1), psel = tid >> LBM;
            int gm = m0 + m;
            #pragma unroll
            for (int t = 0; t < PA; ++t) {
                int p = psel * PA + t;
                int kk = ((p >> 2) << 3) + (p & 3);
                va[2 * t]     = (gm < M) ? A[(long)(k0 + kk) * lda + gm] : 0.f;
                va[2 * t + 1] = (gm < M) ? A[(long)(k0 + kk + 4) * lda + gm] : 0.f;
            }
        }
    };
    auto loadB = [&](int k0) {
        if (TB) {
            #pragma unroll
            for (int t = 0; t < NB; ++t) {
                int i = tid + t * 256;
                int k = i & 15, n = i >> 4;
                int gn = n0 + n;
                vb[t] = (gn < N) ? Bm[(long)gn * ldb + k0 + k] : 0.f;
            }
        } else {
            int n = tid & (BN - 1), psel = tid >> LBN;
            int gn = n0 + n;
            #pragma unroll
            for (int t = 0; t < PB; ++t) {
                int p = psel * PB + t;
                int kk = ((p >> 2) << 3) + (p & 3);
                vb[2 * t]     = (gn < N) ? Bm[(long)(k0 + kk) * ldb + gn] : 0.f;
                vb[2 * t + 1] = (gn < N) ? Bm[(long)(k0 + kk + 4) * ldb + gn] : 0.f;
            }
        }
    };
    auto storeA = [&](int buf) {
        if (!TA) {
            #pragma unroll
            for (int t = 0; t < NA; ++t) {
                int i = tid + t * 256;
                int k = i & 15, m = i >> 4;
                int g = k >> 3, kq = k & 3, half = (k >> 2) & 1;
                unsigned hi, lo;
                f2tf_split(va[t], hi, lo);
                float* base = &As[((long)(buf * BM + m)) * SSTR + g * 16 + kq * 4];
                base[half]     = __uint_as_float(hi);
                base[2 + half] = __uint_as_float(lo);
            }
        } else {
            int m = tid & (BM - 1), psel = tid >> LBM;
            #pragma unroll
            for (int t = 0; t < PA; ++t) {
                int p = psel * PA + t;
                int g = p >> 2, kq = p & 3;
                unsigned h0, l0, h1, l1;
                f2tf_split(va[2 * t], h0, l0);
                f2tf_split(va[2 * t + 1], h1, l1);
                uint4 v = make_uint4(h0, h1, l0, l1);
                *(uint4*)&As[((long)(buf * BM + m)) * SSTR + g * 16 + kq * 4] = v;
            }
        }
    };
    auto storeB = [&](int buf) {
        if (TB) {
            #pragma unroll
            for (int t = 0; t < NB; ++t) {
                int i = tid + t * 256;
                int k = i & 15, n = i >> 4;
                int g = k >> 3, kq = k & 3, half = (k >> 2) & 1;
                unsigned hi, lo;
                f2tf_split(vb[t], hi, lo);
                float* base = &Bs[((long)(buf * BN + n)) * SSTR + g * 16 + kq * 4];
                base[half]     = __uint_as_float(hi);
                base[2 + half] = __uint_as_float(lo);
            }
        } else {
            int n = tid & (BN - 1), psel = tid >> LBN;
            #pragma unroll
            for (int t = 0; t < PB; ++t) {
                int p = psel * PB + t;
                int g = p >> 2, kq = p & 3;
                unsigned h0, l0, h1, l1;
                f2tf_split(vb[2 * t], h0, l0);
                f2tf_split(vb[2 * t + 1], h1, l1);
                uint4 v = make_uint4(h0, h1, l0, l1);
                *(uint4*)&Bs[((long)(buf * BN + n)) * SSTR + g * 16 + kq * 4] = v;
            }
        }
    };
    auto compute = [&](int buf) {
        #pragma unroll
        for (int g = 0; g < 2; ++g) {
            uint4 a0[MI], a1[MI], bv[NJ];
            #pragma unroll
            for (int i = 0; i < MI; ++i) {
                int r = wm + i * 16 + (lane >> 2);
                a0[i] = *(const uint4*)&As[((long)(buf * BM + r)) * SSTR + g * 16 + ((lane & 3) << 2)];
                a1[i] = *(const uint4*)&As[((long)(buf * BM + r + 8)) * SSTR + g * 16 + ((lane & 3) << 2)];
            }
            #pragma unroll
            for (int j = 0; j < NJ; ++j) {
                int c = wn + j * 8 + (lane >> 2);
                bv[j] = *(const uint4*)&Bs[((long)(buf * BN + c)) * SSTR + g * 16 + ((lane & 3) << 2)];
            }
            unsigned aH[MI][4], aL[MI][4];
            #pragma unroll
            for (int i = 0; i < MI; ++i) {
                aH[i][0] = a0[i].x; aH[i][1] = a1[i].x; aH[i][2] = a0[i].y; aH[i][3] = a1[i].y;
                aL[i][0] = a0[i].z; aL[i][1] = a1[i].z; aL[i][2] = a0[i].w; aL[i][3] = a1[i].w;
            }
            #pragma unroll
            for (int j = 0; j < NJ; ++j) {
                unsigned bH[2] = { bv[j].x, bv[j].y };
                unsigned bL[2] = { bv[j].z, bv[j].w };
                #pragma unroll
                for (int i = 0; i < MI; ++i) {
                    mma_tf32(acc[i][j], aH[i], bH);
                    mma_tf32(acc[i][j], aH[i], bL);
                    mma_tf32(acc[i][j], aL[i], bH);
                }
            }
        }
    };

    int buf = 0;
    loadA(0); loadB(0);
    storeA(0); storeB(0);
    __syncthreads();

    for (int k0 = 0; k0 < Kd; k0 += 16) {
        bool more = (k0 + 16) < Kd;
        if (more) { loadA(k0 + 16); loadB(k0 + 16); }
        compute(buf);
        if (more) {
            storeA(buf ^ 1); storeB(buf ^ 1);
            __syncthreads();
            buf ^= 1;
        }
    }

    const float gmv = gammaPtr ? *gammaPtr : 1.f;
    #pragma unroll
    for (int i = 0; i < MI; ++i) {
        int r0 = m0 + wm + i * 16 + (lane >> 2);
        int r1 = r0 + 8;
        float sc0 = 1.f, bi0 = 0.f, sc1 = 1.f, bi1 = 0.f;
        if (scaleC) { if (r0 < M) sc0 = scaleC[r0]; if (r1 < M) sc1 = scaleC[r1]; }
        if (biasC)  { if (r0 < M) bi0 = biasC[r0];  if (r1 < M) bi1 = biasC[r1]; }
        #pragma unroll
        for (int j = 0; j < NJ; ++j) {
            int c = n0 + wn + j * 8 + ((lane & 3) << 1);
            float4 v = acc[i][j];
            if (r0 < M) {
                float x0 = v.x * sc0 + bi0, x1 = v.y * sc0 + bi0;
                if (relu) { x0 = fmaxf(x0, 0.f); x1 = fmaxf(x1, 0.f); }
                if (resid) {
                    if (c < N)     x0 = x0 * gmv + resid[(long)r0 * N + c];
                    if (c + 1 < N) x1 = x1 * gmv + resid[(long)r0 * N + c + 1];
                }
                if (c < N)     C[(long)r0 * N + c]     = x0;
                if (c + 1 < N) C[(long)r0 * N + c + 1] = x1;
            }
            if (r1 < M) {
                float y0 = v.z * sc1 + bi1, y1 = v.w * sc1 + bi1;
                if (relu) { y0 = fmaxf(y0, 0.f); y1 = fmaxf(y1, 0.f); }
                if (resid) {
                    if (c < N)     y0 = y0 * gmv + resid[(long)r1 * N + c];
                    if (c + 1 < N) y1 = y1 * gmv + resid[(long)r1 * N + c + 1];
                }
                if (c < N)     C[(long)r1 * N + c]     = y0;
                if (c + 1 < N) C[(long)r1 * N + c + 1] = y1;
            }
        }
    }
}

// ---------------- pointwise kernels -----------------------------------------
__global__ void tshuffle_kernel(const float* __restrict__ pf,
                                const float* __restrict__ gw,
                                const float* __restrict__ gb,
                                float* __restrict__ out)
{
    int idx = blockIdx.x * blockDim.x + threadIdx.x;
    if (idx >= B_SZ * COUT * HW) return;
    int c = (idx / HW) % COUT;
    float s = gb[c];
    #pragma unroll
    for (int k = 0; k < K_FR; ++k)
        s = fmaf(pf[(long)k * (B_SZ * COUT * HW) + idx], gw[c * K_FR + k], s);
    out[idx] = s;
}

__global__ void bnprep_kernel(const float* __restrict__ p,
                              float* __restrict__ a, float* __restrict__ b)
{
    int c = blockIdx.x * blockDim.x + threadIdx.x;
    if (c >= COUT) return;
    float g = p[c], be = p[COUT + c], m = p[2 * COUT + c], v = p[3 * COUT + c];
    float s = g * rsqrtf(v + 1e-5f);
    a[c] = s;
    b[c] = be - m * s;
}

__global__ void im2col_kernel(const float* __restrict__ x, float* __restrict__ col)
{
    long idx = (long)blockIdx.x * blockDim.x + threadIdx.x;
    const long total = (long)B_SZ * COUT * 9 * HW;
    if (idx >= total) return;
    int n = (int)(idx % HW);
    long r = idx / HW;
    int t = (int)(r % 9);  r /= 9;
    int ci = (int)(r % COUT);
    int b = (int)(r / COUT);
    int h = n / W_, w = n % W_;
    int hh = h + t / 3 - 1, ww = w + t % 3 - 1;
    float v = 0.f;
    if (hh >= 0 && hh < H_ && ww >= 0 && ww < W_)
        v = x[((long)b * COUT + ci) * HW + hh * W_ + ww];
    col[idx] = v;
}

__global__ void softmax_kernel(float* __restrict__ S, int len, float scale)
{
    float* p = S + (long)blockIdx.x * len;
    __shared__ float red[256];
    int tid = threadIdx.x;
    float mx = -1e30f;
    for (int j = tid; j < len; j += 256) mx = fmaxf(mx, p[j] * scale);
    red[tid] = mx; __syncthreads();
    for (int s = 128; s > 0; s >>= 1) {
        if (tid < s) red[tid] = fmaxf(red[tid], red[tid + s]);
        __syncthreads();
    }
    mx = red[0]; __syncthreads();
    float sum = 0.f;
    for (int j = tid; j < len; j += 256) {
        float e = expf(p[j] * scale - mx);
        p[j] = e; sum += e;
    }
    red[tid] = sum; __syncthreads();
    for (int s = 128; s > 0; s >>= 1) {
        if (tid < s) red[tid] += red[tid + s];
        __syncthreads();
    }
    float inv = 1.f / red[0];
    for (int j = tid; j < len; j += 256) p[j] *= inv;
}

__global__ void concat_kernel(const float* __restrict__ kf,
                              const float* __restrict__ x,
                              float* __restrict__ cat)
{
    long idx = (long)blockIdx.x * blockDim.x + threadIdx.x;
    const long total = (long)B_SZ * 2 * COUT * HW;
    if (idx >= total) return;
    int n = (int)(idx % HW);
    long r = idx / HW;
    int c = (int)(r % (2 * COUT));
    int b = (int)(r / (2 * COUT));
    cat[idx] = (c < COUT) ? kf[((long)b * COUT + c) * HW + n]
                          : x[((long)b * COUT + (c - COUT)) * HW + n];
}

// ---------------- host-side helpers -----------------------------------------
// big=1 -> 128x128 tile; big=0 -> 64x128 tile (for M<=256 launches)
static void launch_gemm(int big, bool TA, bool TB,
                        const float* A, const float* B, float* C,
                        int M, int N, int Kd, int lda, int ldb,
                        long aS, int aDiv, long bS, long cS,
                        const float* sc, const float* bi, long biS,
                        int relu, const float* gp,
                        const float* res, long rS, int Z)
{
    dim3 block(256);
    if (big) {
        const int SMB = (2 * 128 + 2 * 128) * SSTR * 4;   // 96 KB
        dim3 grid((N + 127) / 128, (M + 127) / 128, Z);
        if (!TA && !TB) {
            cudaFuncSetAttribute(gemm_tc<128,128,false,false>,
                                 cudaFuncAttributeMaxDynamicSharedMemorySize, SMB);
            gemm_tc<128,128,false,false><<<grid, block, SMB>>>(A, B, C, M, N, Kd, lda, ldb,
                aS, aDiv, bS, cS, sc, bi, biS, relu, gp, res, rS);
        } else if (TA && !TB) {
            cudaFuncSetAttribute(gemm_tc<128,128,true,false>,
                                 cudaFuncAttributeMaxDynamicSharedMemorySize, SMB);
            gemm_tc<128,128,true,false><<<grid, block, SMB>>>(A, B, C, M, N, Kd, lda, ldb,
                aS, aDiv, bS, cS, sc, bi, biS, relu, gp, res, rS);
        } else {
            cudaFuncSetAttribute(gemm_tc<128,128,false,true>,
                                 cudaFuncAttributeMaxDynamicSharedMemorySize, SMB);
            gemm_tc<128,128,false,true><<<grid, block, SMB>>>(A, B, C, M, N, Kd, lda, ldb,
                aS, aDiv, bS, cS, sc, bi, biS, relu, gp, res, rS);
        }
    } else {
        const int SMB = (2 * 64 + 2 * 128) * SSTR * 4;    // 72 KB
        dim3 grid((N + 127) / 128, (M + 63) / 64, Z);
        if (!TA && !TB) {
            cudaFuncSetAttribute(gemm_tc<64,128,false,false>,
                                 cudaFuncAttributeMaxDynamicSharedMemorySize, SMB);
            gemm_tc<64,128,false,false><<<grid, block, SMB>>>(A, B, C, M, N, Kd, lda, ldb,
                aS, aDiv, bS, cS, sc, bi, biS, relu, gp, res, rS);
        } else if (!TA && TB) {
            cudaFuncSetAttribute(gemm_tc<64,128,false,true>,
                                 cudaFuncAttributeMaxDynamicSharedMemorySize, SMB);
            gemm_tc<64,128,false,true><<<grid, block, SMB>>>(A, B, C, M, N, Kd, lda, ldb,
                aS, aDiv, bS, cS, sc, bi, biS, relu, gp, res, rS);
        } else {
            cudaFuncSetAttribute(gemm_tc<64,128,true,false>,
                                 cudaFuncAttributeMaxDynamicSharedMemorySize, SMB);
            gemm_tc<64,128,true,false><<<grid, block, SMB>>>(A, B, C, M, N, Kd, lda, ldb,
                aS, aDiv, bS, cS, sc, bi, biS, relu, gp, res, rS);
        }
    }
}

extern "C" void kernel_launch(void* const* d_in, const int* in_sizes, int n_in,
                              void* d_out, int out_size)
{
    const float* feats    = (const float*)d_in[0];
    const float* proj_w   = (const float*)d_in[1];
    const float* proj_b   = (const float*)d_in[2];
    const float* ts_gw    = (const float*)d_in[3];
    const float* ts_gb    = (const float*)d_in[4];
    const float* ts_w3    = (const float*)d_in[5];
    const float* ts_bn    = (const float*)d_in[6];
    const float* ssam_w1  = (const float*)d_in[7];
    const float* ssam_b1  = (const float*)d_in[8];
    const float* ssam_w2  = (const float*)d_in[9];
    const float* ssam_b2  = (const float*)d_in[10];
    const float* ssam_g   = (const float*)d_in[11];
    const float* csam_w1  = (const float*)d_in[12];
    const float* csam_b1  = (const float*)d_in[13];
    const float* csam_w2  = (const float*)d_in[14];
    const float* csam_b2  = (const float*)d_in[15];
    const float* fuse_w1  = (const float*)d_in[16];
    const float* fuse_bn1 = (const float*)d_in[17];
    const float* fuse_w2  = (const float*)d_in[18];
    const float* fuse_bn2 = (const float*)d_in[19];
    const float* fcsam_w1 = (const float*)d_in[20];
    const float* fcsam_b1 = (const float*)d_in[21];
    const float* fcsam_w2 = (const float*)d_in[22];
    const float* fcsam_b2 = (const float*)d_in[23];
    const float* fuse_w4  = (const float*)d_in[24];
    const float* fuse_bn4 = (const float*)d_in[25];
    float* out = (float*)d_out;

    float *pf, *x, *x2, *o1, *h, *aS_, *aC_, *col, *cat, *bnA, *bnB;
    cudaGetSymbolAddress((void**)&pf,  g_pf);
    cudaGetSymbolAddress((void**)&x,   g_x);
    cudaGetSymbolAddress((void**)&x2,  g_x2);
    cudaGetSymbolAddress((void**)&o1,  g_o1);
    cudaGetSymbolAddress((void**)&h,   g_h);
    cudaGetSymbolAddress((void**)&aS_, g_aS);
    cudaGetSymbolAddress((void**)&aC_, g_aC);
    cudaGetSymbolAddress((void**)&col, g_col);
    cudaGetSymbolAddress((void**)&cat, g_cat);
    cudaGetSymbolAddress((void**)&bnA, g_bnA);
    cudaGetSymbolAddress((void**)&bnB, g_bnB);

    const long SP  = (long)COUT * HW;
    const long SPH = (long)C4V * HW;
    const long SPS = (long)HW * HW;
    const long SPC = (long)COUT * COUT;
    const long SPCOL = (long)COUT * 9 * HW;
    const long SPCAT = (long)2 * COUT * HW;

    // 1. per-frame 1x1 projection (z=64 -> plenty of blocks at 128x128)
    launch_gemm(1, false, false, proj_w, feats, pf, COUT, HW, CIN, CIN, HW,
                (long)COUT * CIN, B_SZ, (long)CIN * HW, SP,
                nullptr, proj_b, COUT, 0, nullptr, nullptr, 0, K_FR * B_SZ);

    // 2. temporal shuffle + grouped 1x1 -> x
    {
        int total = B_SZ * COUT * HW;
        tshuffle_kernel<<<(total + 255) / 256, 256>>>(pf, ts_gw, ts_gb, x);
    }

    // 3. 3x3 conv + BN -> x2
    bnprep_kernel<<<1, 256>>>(ts_bn, bnA, bnB);
    {
        long total = (long)B_SZ * SPCOL;
        im2col_kernel<<<(int)((total + 255) / 256), 256>>>(x, col);
    }
    launch_gemm(0, false, false, ts_w3, col, x2, COUT, HW, COUT * 9, COUT * 9, HW,
                0, 1, SPCOL, SP, bnA, bnB, 0, 0, nullptr, nullptr, 0, B_SZ);

    // 4. spatial self-attention (input x2, output x)
    launch_gemm(1, true, false, x2, x2, aS_, HW, HW, COUT, HW, HW,
                SP, 1, SP, SPS, nullptr, nullptr, 0, 0, nullptr, nullptr, 0, B_SZ);
    softmax_kernel<<<B_SZ * HW, 256>>>(aS_, HW, 0.0625f);
    launch_gemm(0, false, true, x2, aS_, o1, COUT, HW, HW, HW, HW,
                SP, 1, SPS, SP, nullptr, nullptr, 0, 0, nullptr, nullptr, 0, B_SZ);
    launch_gemm(1, false, false, ssam_w1, o1, h, C4V, HW, COUT, COUT, HW,
                0, 1, SP, SPH, nullptr, ssam_b1, 0, 1, nullptr, nullptr, 0, B_SZ);
    launch_gemm(0, false, false, ssam_w2, h, x, COUT, HW, C4V, C4V, HW,
                0, 1, SPH, SP, nullptr, ssam_b2, 0, 0, ssam_g, x2, SP, B_SZ);

    // 5. channel self-attention (input x, output x2)
    launch_gemm(0, false, true, x, x, aC_, COUT, COUT, HW, HW, HW,
                SP, 1, SP, SPC, nullptr, nullptr, 0, 0, nullptr, nullptr, 0, B_SZ);
    softmax_kernel<<<B_SZ * COUT, 256>>>(aC_, COUT, 0.0625f);
    launch_gemm(0, false, false, aC_, x, o1, COUT, HW, COUT, COUT, HW,
                SPC, 1, SP, SP, nullptr, nullptr, 0, 0, nullptr, nullptr, 0, B_SZ);
    launch_gemm(1, false, false, csam_w1, o1, h, C4V, HW, COUT, COUT, HW,
                0, 1, SP, SPH, nullptr, csam_b1, 0, 1, nullptr, nullptr, 0, B_SZ);
    launch_gemm(0, false, false, csam_w2, h, x2, COUT, HW, C4V, C4V, HW,
                0, 1, SPH, SP, nullptr, csam_b2, 0, 0, nullptr, x, SP, B_SZ);

    // 6. fuse: concat keyframe feat (pf[K-1]) with x2
    {
        long total = (long)B_SZ * SPCAT;
        concat_kernel<<<(int)((total + 255) / 256), 256>>>(
            pf + (long)(K_FR - 1) * B_SZ * SP, x2, cat);
    }
    bnprep_kernel<<<1, 256>>>(fuse_bn1, bnA, bnB);
    launch_gemm(0, false, false, fuse_w1, cat, x, COUT, HW, 2 * COUT, 2 * COUT, HW,
                0, 1, SPCAT, SP, bnA, bnB, 0, 1, nullptr, nullptr, 0, B_SZ);

    // 7. 3x3 conv + BN + relu -> x2
    bnprep_kernel<<<1, 256>>>(fuse_bn2, bnA, bnB);
    {
        long total = (long)B_SZ * SPCOL;
        im2col_kernel<<<(int)((total + 255) / 256), 256>>>(x, col);
    }
    launch_gemm(0, false, false, fuse_w2, col, x2, COUT, HW, COUT * 9, COUT * 9, HW,
                0, 1, SPCOL, SP, bnA, bnB, 0, 1, nullptr, nullptr, 0, B_SZ);

    // 8. channel self-attention (input x2, output x)
    launch_gemm(0, false, true, x2, x2, aC_, COUT, COUT, HW, HW, HW,
                SP, 1, SP, SPC, nullptr, nullptr, 0, 0, nullptr, nullptr, 0, B_SZ);
    softmax_kernel<<<B_SZ * COUT, 256>>>(aC_, COUT, 0.0625f);
    launch_gemm(0, false, false, aC_, x2, o1, COUT, HW, COUT, COUT, HW,
                SPC, 1, SP, SP, nullptr, nullptr, 0, 0, nullptr, nullptr, 0, B_SZ);
    launch_gemm(1, false, false, fcsam_w1, o1, h, C4V, HW, COUT, COUT, HW,
                0, 1, SP, SPH, nullptr, fcsam_b1, 0, 1, nullptr, nullptr, 0, B_SZ);
    launch_gemm(0, false, false, fcsam_w2, h, x, COUT, HW, C4V, C4V, HW,
                0, 1, SPH, SP, nullptr, fcsam_b2, 0, 0, nullptr, x2, SP, B_SZ);

    // 9. final 3x3 conv + BN + relu -> d_out
    bnprep_kernel<<<1, 256>>>(fuse_bn4, bnA, bnB);
    {
        long total = (long)B_SZ * SPCOL;
        im2col_kernel<<<(int)((total + 255) / 256), 256>>>(x, col);
    }
    launch_gemm(0, false, false, fuse_w4, col, out, COUT, HW, COUT * 9, COUT * 9, HW,
                0, 1, SPCOL, SP, bnA, bnB, 0, 1, nullptr, nullptr, 0, B_SZ);
}

// round 5
// speedup vs baseline: 1.5395x; 1.0071x over previous
#include <cuda_runtime.h>
#include <math.h>

#define K_FR 8
#define B_SZ 8
#define CIN  512
#define COUT 256
#define H_   28
#define W_   28
#define HW   784
#define C4V  1024

// ---------------- scratch (device globals; no allocation at runtime) --------
__device__ float g_pf  [K_FR * B_SZ * COUT * HW];
__device__ float g_x   [B_SZ * COUT * HW];
__device__ float g_x2  [B_SZ * COUT * HW];
__device__ float g_o1  [B_SZ * COUT * HW];
__device__ float g_h   [B_SZ * C4V * HW];
__device__ float g_aS  [B_SZ * HW * HW];
__device__ float g_aC  [B_SZ * COUT * COUT];
__device__ float g_col [B_SZ * COUT * 9 * HW];
__device__ float g_cat [B_SZ * 2 * COUT * HW];
__device__ float g_bnA [COUT];
__device__ float g_bnB [COUT];

// ---------------- 3xTF32 tensor-core GEMM, split-at-store ------------------
// Inner loop is pure LDS.128 + HMMA, with the 3 compensation MMAs issued in
// SEPARATE PASSES over all (i,j) accumulators so no back-to-back RAW on the
// same accumulator (HMMA latency hidden even at 2 warps/SMSP).
// smem value layout: float4 {hi(k), hi(k+4), lo(k), lo(k+4)}, row stride 48.
// TA: A stored [K,M]; else [M,K].  TB: B stored [N,K]; else [K,N].
// epilogue: v = acc*scale[m]+bias[m]; relu; v = v*gamma + resid[m,n]
// Requires Kd % 16 == 0 (all call sites: 256/512/784/1024/2304).

__device__ __forceinline__ unsigned f2tf(float f) {
    unsigned u;
    asm("cvt.rna.tf32.f32 %0, %1;" : "=r"(u) : "f"(f));
    return u;
}
__device__ __forceinline__ void f2tf_split(float f, unsigned& hi, unsigned& lo) {
    hi = f2tf(f);
    lo = f2tf(f - __uint_as_float(hi));
}
__device__ __forceinline__ void mma_tf32(float4& d, const unsigned a[4], const unsigned b[2]) {
    asm volatile(
        "mma.sync.aligned.m16n8k8.row.col.f32.tf32.tf32.f32 "
        "{%0,%1,%2,%3}, {%4,%5,%6,%7}, {%8,%9}, {%0,%1,%2,%3};"
        : "+f"(d.x), "+f"(d.y), "+f"(d.z), "+f"(d.w)
        : "r"(a[0]), "r"(a[1]), "r"(a[2]), "r"(a[3]), "r"(b[0]), "r"(b[1]));
}

#define SSTR 48   // smem row stride in floats

template <int BM, int BN, bool TA, bool TB>
__global__ void __launch_bounds__(256) gemm_tc(
    const float* __restrict__ A, const float* __restrict__ Bm, float* __restrict__ C,
    int M, int N, int Kd, int lda, int ldb,
    long aS, int aDiv, long bS, long cS,
    const float* __restrict__ scaleC, const float* __restrict__ biasC, long biS,
    int relu, const float* __restrict__ gammaPtr,
    const float* __restrict__ resid, long rS)
{
    extern __shared__ float sm[];
    float* As = sm;                    // [2][BM][SSTR]
    float* Bs = sm + 2 * BM * SSTR;    // [2][BN][SSTR]

    const int z = blockIdx.z;
    A  += (long)(z / aDiv) * aS;
    Bm += (long)z * bS;
    C  += (long)z * cS;
    if (biasC) biasC += (long)(z / aDiv) * biS;
    if (resid) resid += (long)z * rS;

    const int tid  = threadIdx.x;
    const int lane = tid & 31, warp = tid >> 5;
    constexpr int MI = BM / 32, NJ = BN / 32;
    constexpr int LBM = (BM == 128) ? 7 : 6;
    constexpr int LBN = (BN == 128) ? 7 : 6;
    constexpr int NA = BM * 16 / 256;   // values per thread (A tile)
    constexpr int PA = NA / 2;          // pairs per thread (TA path)
    constexpr int NB = BN * 16 / 256;
    constexpr int PB = NB / 2;
    const int wm = (warp >> 2) * (BM / 2);
    const int wn = (warp & 3) * (BN / 4);
    const int m0 = blockIdx.y * BM, n0 = blockIdx.x * BN;

    float4 acc[MI][NJ];
    #pragma unroll
    for (int i = 0; i < MI; ++i)
        #pragma unroll
        for (int j = 0; j < NJ; ++j)
            acc[i][j] = make_float4(0.f, 0.f, 0.f, 0.f);

    float va[NA], vb[NB];

    auto loadA = [&](int k0) {
        if (!TA) {
            #pragma unroll
            for (int t = 0; t < NA; ++t) {
                int i = tid + t * 256;
                int k = i & 15, m = i >> 4;
                int gm = m0 + m;
                va[t] = (gm < M) ? A[(long)gm * lda + k0 + k] : 0.f;
            }
        } else {
            int m = tid & (BM - 1), psel = tid >> LBM;
            int gm = m0 + m;
            #pragma unroll
            for (int t = 0; t < PA; ++t) {
                int p = psel * PA + t;
                int kk = ((p >> 2) << 3) + (p & 3);
                va[2 * t]     = (gm < M) ? A[(long)(k0 + kk) * lda + gm] : 0.f;
                va[2 * t + 1] = (gm < M) ? A[(long)(k0 + kk + 4) * lda + gm] : 0.f;
            }
        }
    };
    auto loadB = [&](int k0) {
        if (TB) {
            #pragma unroll
            for (int t = 0; t < NB; ++t) {
                int i = tid + t * 256;
                int k = i & 15, n = i >> 4;
                int gn = n0 + n;
                vb[t] = (gn < N) ? Bm[(long)gn * ldb + k0 + k] : 0.f;
            }
        } else {
            int n = tid & (BN - 1), psel = tid >> LBN;
            int gn = n0 + n;
            #pragma unroll
            for (int t = 0; t < PB; ++t) {
                int p = psel * PB + t;
                int kk = ((p >> 2) << 3) + (p & 3);
                vb[2 * t]     = (gn < N) ? Bm[(long)(k0 + kk) * ldb + gn] : 0.f;
                vb[2 * t + 1] = (gn < N) ? Bm[(long)(k0 + kk + 4) * ldb + gn] : 0.f;
            }
        }
    };
    auto storeA = [&](int buf) {
        if (!TA) {
            #pragma unroll
            for (int t = 0; t < NA; ++t) {
                int i = tid + t * 256;
                int k = i & 15, m = i >> 4;
                int g = k >> 3, kq = k & 3, half = (k >> 2) & 1;
                unsigned hi, lo;
                f2tf_split(va[t], hi, lo);
                float* base = &As[((long)(buf * BM + m)) * SSTR + g * 16 + kq * 4];
                base[half]     = __uint_as_float(hi);
                base[2 + half] = __uint_as_float(lo);
            }
        } else {
            int m = tid & (BM - 1), psel = tid >> LBM;
            #pragma unroll
            for (int t = 0; t < PA; ++t) {
                int p = psel * PA + t;
                int g = p >> 2, kq = p & 3;
                unsigned h0, l0, h1, l1;
                f2tf_split(va[2 * t], h0, l0);
                f2tf_split(va[2 * t + 1], h1, l1);
                uint4 v = make_uint4(h0, h1, l0, l1);
                *(uint4*)&As[((long)(buf * BM + m)) * SSTR + g * 16 + kq * 4] = v;
            }
        }
    };
    auto storeB = [&](int buf) {
        if (TB) {
            #pragma unroll
            for (int t = 0; t < NB; ++t) {
                int i = tid + t * 256;
                int k = i & 15, n = i >> 4;
                int g = k >> 3, kq = k & 3, half = (k >> 2) & 1;
                unsigned hi, lo;
                f2tf_split(vb[t], hi, lo);
                float* base = &Bs[((long)(buf * BN + n)) * SSTR + g * 16 + kq * 4];
                base[half]     = __uint_as_float(hi);
                base[2 + half] = __uint_as_float(lo);
            }
        } else {
            int n = tid & (BN - 1), psel = tid >> LBN;
            #pragma unroll
            for (int t = 0; t < PB; ++t) {
                int p = psel * PB + t;
                int g = p >> 2, kq = p & 3;
                unsigned h0, l0, h1, l1;
                f2tf_split(vb[2 * t], h0, l0);
                f2tf_split(vb[2 * t + 1], h1, l1);
                uint4 v = make_uint4(h0, h1, l0, l1);
                *(uint4*)&Bs[((long)(buf * BN + n)) * SSTR + g * 16 + kq * 4] = v;
            }
        }
    };
    auto compute = [&](int buf) {
        #pragma unroll
        for (int g = 0; g < 2; ++g) {
            uint4 a0[MI], a1[MI], bv[NJ];
            #pragma unroll
            for (int i = 0; i < MI; ++i) {
                int r = wm + i * 16 + (lane >> 2);
                a0[i] = *(const uint4*)&As[((long)(buf * BM + r)) * SSTR + g * 16 + ((lane & 3) << 2)];
                a1[i] = *(const uint4*)&As[((long)(buf * BM + r + 8)) * SSTR + g * 16 + ((lane & 3) << 2)];
            }
            #pragma unroll
            for (int j = 0; j < NJ; ++j) {
                int c = wn + j * 8 + (lane >> 2);
                bv[j] = *(const uint4*)&Bs[((long)(buf * BN + c)) * SSTR + g * 16 + ((lane & 3) << 2)];
            }
            unsigned aH[MI][4], aL[MI][4], bH[NJ][2], bL[NJ][2];
            #pragma unroll
            for (int i = 0; i < MI; ++i) {
                aH[i][0] = a0[i].x; aH[i][1] = a1[i].x; aH[i][2] = a0[i].y; aH[i][3] = a1[i].y;
                aL[i][0] = a0[i].z; aL[i][1] = a1[i].z; aL[i][2] = a0[i].w; aL[i][3] = a1[i].w;
            }
            #pragma unroll
            for (int j = 0; j < NJ; ++j) {
                bH[j][0] = bv[j].x; bH[j][1] = bv[j].y;
                bL[j][0] = bv[j].z; bL[j][1] = bv[j].w;
            }
            // Three passes: each accumulator's dependent reuse is MI*NJ MMAs
            // apart -> HMMA RAW latency fully hidden.
            #pragma unroll
            for (int j = 0; j < NJ; ++j)
                #pragma unroll
                for (int i = 0; i < MI; ++i)
                    mma_tf32(acc[i][j], aH[i], bH[j]);   // hi*hi
            #pragma unroll
            for (int j = 0; j < NJ; ++j)
                #pragma unroll
                for (int i = 0; i < MI; ++i)
                    mma_tf32(acc[i][j], aH[i], bL[j]);   // hi*lo
            #pragma unroll
            for (int j = 0; j < NJ; ++j)
                #pragma unroll
                for (int i = 0; i < MI; ++i)
                    mma_tf32(acc[i][j], aL[i], bH[j]);   // lo*hi
        }
    };

    int buf = 0;
    loadA(0); loadB(0);
    storeA(0); storeB(0);
    __syncthreads();

    for (int k0 = 0; k0 < Kd; k0 += 16) {
        bool more = (k0 + 16) < Kd;
        if (more) { loadA(k0 + 16); loadB(k0 + 16); }
        compute(buf);
        if (more) {
            storeA(buf ^ 1); storeB(buf ^ 1);
            __syncthreads();
            buf ^= 1;
        }
    }

    const float gmv = gammaPtr ? *gammaPtr : 1.f;
    #pragma unroll
    for (int i = 0; i < MI; ++i) {
        int r0 = m0 + wm + i * 16 + (lane >> 2);
        int r1 = r0 + 8;
        float sc0 = 1.f, bi0 = 0.f, sc1 = 1.f, bi1 = 0.f;
        if (scaleC) { if (r0 < M) sc0 = scaleC[r0]; if (r1 < M) sc1 = scaleC[r1]; }
        if (biasC)  { if (r0 < M) bi0 = biasC[r0];  if (r1 < M) bi1 = biasC[r1]; }
        #pragma unroll
        for (int j = 0; j < NJ; ++j) {
            int c = n0 + wn + j * 8 + ((lane & 3) << 1);
            float4 v = acc[i][j];
            if (r0 < M) {
                float x0 = v.x * sc0 + bi0, x1 = v.y * sc0 + bi0;
                if (relu) { x0 = fmaxf(x0, 0.f); x1 = fmaxf(x1, 0.f); }
                if (resid) {
                    if (c < N)     x0 = x0 * gmv + resid[(long)r0 * N + c];
                    if (c + 1 < N) x1 = x1 * gmv + resid[(long)r0 * N + c + 1];
                }
                if (c < N)     C[(long)r0 * N + c]     = x0;
                if (c + 1 < N) C[(long)r0 * N + c + 1] = x1;
            }
            if (r1 < M) {
                float y0 = v.z * sc1 + bi1, y1 = v.w * sc1 + bi1;
                if (relu) { y0 = fmaxf(y0, 0.f); y1 = fmaxf(y1, 0.f); }
                if (resid) {
                    if (c < N)     y0 = y0 * gmv + resid[(long)r1 * N + c];
                    if (c + 1 < N) y1 = y1 * gmv + resid[(long)r1 * N + c + 1];
                }
                if (c < N)     C[(long)r1 * N + c]     = y0;
                if (c + 1 < N) C[(long)r1 * N + c + 1] = y1;
            }
        }
    }
}

// ---------------- pointwise kernels -----------------------------------------
__global__ void tshuffle_kernel(const float* __restrict__ pf,
                                const float* __restrict__ gw,
                                const float* __restrict__ gb,
                                float* __restrict__ out)
{
    int idx = blockIdx.x * blockDim.x + threadIdx.x;
    if (idx >= B_SZ * COUT * HW) return;
    int c = (idx / HW) % COUT;
    float s = gb[c];
    #pragma unroll
    for (int k = 0; k < K_FR; ++k)
        s = fmaf(pf[(long)k * (B_SZ * COUT * HW) + idx], gw[c * K_FR + k], s);
    out[idx] = s;
}

__global__ void bnprep_kernel(const float* __restrict__ p,
                              float* __restrict__ a, float* __restrict__ b)
{
    int c = blockIdx.x * blockDim.x + threadIdx.x;
    if (c >= COUT) return;
    float g = p[c], be = p[COUT + c], m = p[2 * COUT + c], v = p[3 * COUT + c];
    float s = g * rsqrtf(v + 1e-5f);
    a[c] = s;
    b[c] = be - m * s;
}

__global__ void im2col_kernel(const float* __restrict__ x, float* __restrict__ col)
{
    long idx = (long)blockIdx.x * blockDim.x + threadIdx.x;
    const long total = (long)B_SZ * COUT * 9 * HW;
    if (idx >= total) return;
    int n = (int)(idx % HW);
    long r = idx / HW;
    int t = (int)(r % 9);  r /= 9;
    int ci = (int)(r % COUT);
    int b = (int)(r / COUT);
    int h = n / W_, w = n % W_;
    int hh = h + t / 3 - 1, ww = w + t % 3 - 1;
    float v = 0.f;
    if (hh >= 0 && hh < H_ && ww >= 0 && ww < W_)
        v = x[((long)b * COUT + ci) * HW + hh * W_ + ww];
    col[idx] = v;
}

__global__ void softmax_kernel(float* __restrict__ S, int len, float scale)
{
    float* p = S + (long)blockIdx.x * len;
    __shared__ float red[256];
    int tid = threadIdx.x;
    float mx = -1e30f;
    for (int j = tid; j < len; j += 256) mx = fmaxf(mx, p[j] * scale);
    red[tid] = mx; __syncthreads();
    for (int s = 128; s > 0; s >>= 1) {
        if (tid < s) red[tid] = fmaxf(red[tid], red[tid + s]);
        __syncthreads();
    }
    mx = red[0]; __syncthreads();
    float sum = 0.f;
    for (int j = tid; j < len; j += 256) {
        float e = expf(p[j] * scale - mx);
        p[j] = e; sum += e;
    }
    red[tid] = sum; __syncthreads();
    for (int s = 128; s > 0; s >>= 1) {
        if (tid < s) red[tid] += red[tid + s];
        __syncthreads();
    }
    float inv = 1.f / red[0];
    for (int j = tid; j < len; j += 256) p[j] *= inv;
}

__global__ void concat_kernel(const float* __restrict__ kf,
                              const float* __restrict__ x,
                              float* __restrict__ cat)
{
    long idx = (long)blockIdx.x * blockDim.x + threadIdx.x;
    const long total = (long)B_SZ * 2 * COUT * HW;
    if (idx >= total) return;
    int n = (int)(idx % HW);
    long r = idx / HW;
    int c = (int)(r % (2 * COUT));
    int b = (int)(r / (2 * COUT));
    cat[idx] = (c < COUT) ? kf[((long)b * COUT + c) * HW + n]
                          : x[((long)b * COUT + (c - COUT)) * HW + n];
}

// ---------------- host-side helpers -----------------------------------------
// big=1 -> 128x128 tile; big=0 -> 64x128 tile (for M<=256 launches)
static void launch_gemm(int big, bool TA, bool TB,
                        const float* A, const float* B, float* C,
                        int M, int N, int Kd, int lda, int ldb,
                        long aS, int aDiv, long bS, long cS,
                        const float* sc, const float* bi, long biS,
                        int relu, const float* gp,
                        const float* res, long rS, int Z)
{
    dim3 block(256);
    if (big) {
        const int SMB = (2 * 128 + 2 * 128) * SSTR * 4;   // 96 KB
        dim3 grid((N + 127) / 128, (M + 127) / 128, Z);
        if (!TA && !TB) {
            cudaFuncSetAttribute(gemm_tc<128,128,false,false>,
                                 cudaFuncAttributeMaxDynamicSharedMemorySize, SMB);
            gemm_tc<128,128,false,false><<<grid, block, SMB>>>(A, B, C, M, N, Kd, lda, ldb,
                aS, aDiv, bS, cS, sc, bi, biS, relu, gp, res, rS);
        } else if (TA && !TB) {
            cudaFuncSetAttribute(gemm_tc<128,128,true,false>,
                                 cudaFuncAttributeMaxDynamicSharedMemorySize, SMB);
            gemm_tc<128,128,true,false><<<grid, block, SMB>>>(A, B, C, M, N, Kd, lda, ldb,
                aS, aDiv, bS, cS, sc, bi, biS, relu, gp, res, rS);
        } else {
            cudaFuncSetAttribute(gemm_tc<128,128,false,true>,
                                 cudaFuncAttributeMaxDynamicSharedMemorySize, SMB);
            gemm_tc<128,128,false,true><<<grid, block, SMB>>>(A, B, C, M, N, Kd, lda, ldb,
                aS, aDiv, bS, cS, sc, bi, biS, relu, gp, res, rS);
        }
    } else {
        const int SMB = (2 * 64 + 2 * 128) * SSTR * 4;    // 72 KB
        dim3 grid((N + 127) / 128, (M + 63) / 64, Z);
        if (!TA && !TB) {
            cudaFuncSetAttribute(gemm_tc<64,128,false,false>,
                                 cudaFuncAttributeMaxDynamicSharedMemorySize, SMB);
            gemm_tc<64,128,false,false><<<grid, block, SMB>>>(A, B, C, M, N, Kd, lda, ldb,
                aS, aDiv, bS, cS, sc, bi, biS, relu, gp, res, rS);
        } else if (!TA && TB) {
            cudaFuncSetAttribute(gemm_tc<64,128,false,true>,
                                 cudaFuncAttributeMaxDynamicSharedMemorySize, SMB);
            gemm_tc<64,128,false,true><<<grid, block, SMB>>>(A, B, C, M, N, Kd, lda, ldb,
                aS, aDiv, bS, cS, sc, bi, biS, relu, gp, res, rS);
        } else {
            cudaFuncSetAttribute(gemm_tc<64,128,true,false>,
                                 cudaFuncAttributeMaxDynamicSharedMemorySize, SMB);
            gemm_tc<64,128,true,false><<<grid, block, SMB>>>(A, B, C, M, N, Kd, lda, ldb,
                aS, aDiv, bS, cS, sc, bi, biS, relu, gp, res, rS);
        }
    }
}

extern "C" void kernel_launch(void* const* d_in, const int* in_sizes, int n_in,
                              void* d_out, int out_size)
{
    const float* feats    = (const float*)d_in[0];
    const float* proj_w   = (const float*)d_in[1];
    const float* proj_b   = (const float*)d_in[2];
    const float* ts_gw    = (const float*)d_in[3];
    const float* ts_gb    = (const float*)d_in[4];
    const float* ts_w3    = (const float*)d_in[5];
    const float* ts_bn    = (const float*)d_in[6];
    const float* ssam_w1  = (const float*)d_in[7];
    const float* ssam_b1  = (const float*)d_in[8];
    const float* ssam_w2  = (const float*)d_in[9];
    const float* ssam_b2  = (const float*)d_in[10];
    const float* ssam_g   = (const float*)d_in[11];
    const float* csam_w1  = (const float*)d_in[12];
    const float* csam_b1  = (const float*)d_in[13];
    const float* csam_w2  = (const float*)d_in[14];
    const float* csam_b2  = (const float*)d_in[15];
    const float* fuse_w1  = (const float*)d_in[16];
    const float* fuse_bn1 = (const float*)d_in[17];
    const float* fuse_w2  = (const float*)d_in[18];
    const float* fuse_bn2 = (const float*)d_in[19];
    const float* fcsam_w1 = (const float*)d_in[20];
    const float* fcsam_b1 = (const float*)d_in[21];
    const float* fcsam_w2 = (const float*)d_in[22];
    const float* fcsam_b2 = (const float*)d_in[23];
    const float* fuse_w4  = (const float*)d_in[24];
    const float* fuse_bn4 = (const float*)d_in[25];
    float* out = (float*)d_out;

    float *pf, *x, *x2, *o1, *h, *aS_, *aC_, *col, *cat, *bnA, *bnB;
    cudaGetSymbolAddress((void**)&pf,  g_pf);
    cudaGetSymbolAddress((void**)&x,   g_x);
    cudaGetSymbolAddress((void**)&x2,  g_x2);
    cudaGetSymbolAddress((void**)&o1,  g_o1);
    cudaGetSymbolAddress((void**)&h,   g_h);
    cudaGetSymbolAddress((void**)&aS_, g_aS);
    cudaGetSymbolAddress((void**)&aC_, g_aC);
    cudaGetSymbolAddress((void**)&col, g_col);
    cudaGetSymbolAddress((void**)&cat, g_cat);
    cudaGetSymbolAddress((void**)&bnA, g_bnA);
    cudaGetSymbolAddress((void**)&bnB, g_bnB);

    const long SP  = (long)COUT * HW;
    const long SPH = (long)C4V * HW;
    const long SPS = (long)HW * HW;
    const long SPC = (long)COUT * COUT;
    const long SPCOL = (long)COUT * 9 * HW;
    const long SPCAT = (long)2 * COUT * HW;

    // 1. per-frame 1x1 projection
    launch_gemm(1, false, false, proj_w, feats, pf, COUT, HW, CIN, CIN, HW,
                (long)COUT * CIN, B_SZ, (long)CIN * HW, SP,
                nullptr, proj_b, COUT, 0, nullptr, nullptr, 0, K_FR * B_SZ);

    // 2. temporal shuffle + grouped 1x1 -> x
    {
        int total = B_SZ * COUT * HW;
        tshuffle_kernel<<<(total + 255) / 256, 256>>>(pf, ts_gw, ts_gb, x);
    }

    // 3. 3x3 conv + BN -> x2
    bnprep_kernel<<<1, 256>>>(ts_bn, bnA, bnB);
    {
        long total = (long)B_SZ * SPCOL;
        im2col_kernel<<<(int)((total + 255) / 256), 256>>>(x, col);
    }
    launch_gemm(0, false, false, ts_w3, col, x2, COUT, HW, COUT * 9, COUT * 9, HW,
                0, 1, SPCOL, SP, bnA, bnB, 0, 0, nullptr, nullptr, 0, B_SZ);

    // 4. spatial self-attention (input x2, output x)
    launch_gemm(1, true, false, x2, x2, aS_, HW, HW, COUT, HW, HW,
                SP, 1, SP, SPS, nullptr, nullptr, 0, 0, nullptr, nullptr, 0, B_SZ);
    softmax_kernel<<<B_SZ * HW, 256>>>(aS_, HW, 0.0625f);
    launch_gemm(0, false, true, x2, aS_, o1, COUT, HW, HW, HW, HW,
                SP, 1, SPS, SP, nullptr, nullptr, 0, 0, nullptr, nullptr, 0, B_SZ);
    launch_gemm(1, false, false, ssam_w1, o1, h, C4V, HW, COUT, COUT, HW,
                0, 1, SP, SPH, nullptr, ssam_b1, 0, 1, nullptr, nullptr, 0, B_SZ);
    launch_gemm(0, false, false, ssam_w2, h, x, COUT, HW, C4V, C4V, HW,
                0, 1, SPH, SP, nullptr, ssam_b2, 0, 0, ssam_g, x2, SP, B_SZ);

    // 5. channel self-attention (input x, output x2)
    launch_gemm(0, false, true, x, x, aC_, COUT, COUT, HW, HW, HW,
                SP, 1, SP, SPC, nullptr, nullptr, 0, 0, nullptr, nullptr, 0, B_SZ);
    softmax_kernel<<<B_SZ * COUT, 256>>>(aC_, COUT, 0.0625f);
    launch_gemm(0, false, false, aC_, x, o1, COUT, HW, COUT, COUT, HW,
                SPC, 1, SP, SP, nullptr, nullptr, 0, 0, nullptr, nullptr, 0, B_SZ);
    launch_gemm(1, false, false, csam_w1, o1, h, C4V, HW, COUT, COUT, HW,
                0, 1, SP, SPH, nullptr, csam_b1, 0, 1, nullptr, nullptr, 0, B_SZ);
    launch_gemm(0, false, false, csam_w2, h, x2, COUT, HW, C4V, C4V, HW,
                0, 1, SPH, SP, nullptr, csam_b2, 0, 0, nullptr, x, SP, B_SZ);

    // 6. fuse: concat keyframe feat (pf[K-1]) with x2
    {
        long total = (long)B_SZ * SPCAT;
        concat_kernel<<<(int)((total + 255) / 256), 256>>>(
            pf + (long)(K_FR - 1) * B_SZ * SP, x2, cat);
    }
    bnprep_kernel<<<1, 256>>>(fuse_bn1, bnA, bnB);
    launch_gemm(0, false, false, fuse_w1, cat, x, COUT, HW, 2 * COUT, 2 * COUT, HW,
                0, 1, SPCAT, SP, bnA, bnB, 0, 1, nullptr, nullptr, 0, B_SZ);

    // 7. 3x3 conv + BN + relu -> x2
    bnprep_kernel<<<1, 256>>>(fuse_bn2, bnA, bnB);
    {
        long total = (long)B_SZ * SPCOL;
        im2col_kernel<<<(int)((total + 255) / 256), 256>>>(x, col);
    }
    launch_gemm(0, false, false, fuse_w2, col, x2, COUT, HW, COUT * 9, COUT * 9, HW,
                0, 1, SPCOL, SP, bnA, bnB, 0, 1, nullptr, nullptr, 0, B_SZ);

    // 8. channel self-attention (input x2, output x)
    launch_gemm(0, false, true, x2, x2, aC_, COUT, COUT, HW, HW, HW,
                SP, 1, SP, SPC, nullptr, nullptr, 0, 0, nullptr, nullptr, 0, B_SZ);
    softmax_kernel<<<B_SZ * COUT, 256>>>(aC_, COUT, 0.0625f);
    launch_gemm(0, false, false, aC_, x2, o1, COUT, HW, COUT, COUT, HW,
                SPC, 1, SP, SP, nullptr, nullptr, 0, 0, nullptr, nullptr, 0, B_SZ);
    launch_gemm(1, false, false, fcsam_w1, o1, h, C4V, HW, COUT, COUT, HW,
                0, 1, SP, SPH, nullptr, fcsam_b1, 0, 1, nullptr, nullptr, 0, B_SZ);
    launch_gemm(0, false, false, fcsam_w2, h, x, COUT, HW, C4V, C4V, HW,
                0, 1, SPH, SP, nullptr, fcsam_b2, 0, 0, nullptr, x2, SP, B_SZ);

    // 9. final 3x3 conv + BN + relu -> d_out
    bnprep_kernel<<<1, 256>>>(fuse_bn4, bnA, bnB);
    {
        long total = (long)B_SZ * SPCOL;
        im2col_kernel<<<(int)((total + 255) / 256), 256>>>(x, col);
    }
    launch_gemm(0, false, false, fuse_w4, col, out, COUT, HW, COUT * 9, COUT * 9, HW,
                0, 1, SPCOL, SP, bnA, bnB, 0, 1, nullptr, nullptr, 0, B_SZ);
}